// round 1
// baseline (speedup 1.0000x reference)
#include <cuda_runtime.h>

#define NB 16384
#define NT 1024
#define HH 64
#define TPB 128

// Shared layout: W2 transposed (W2T[k][j] = W2[j][k]) so a fixed j-group reads
// 8 consecutive floats per k via two LDS.128 (warp-broadcast, conflict-free).
struct __align__(16) SW {
    float W2T[HH][HH];   // 16 KB
    float W1[HH * 2];    // [j][d] row-major as given
    float b1[HH];
    float b2[HH];
    float W3P[HH * 2];   // W3P[2k+d] = W3[d][k]  (pairs for the 2 outputs)
    float b3[2];
    float dt[NT];        // dt[t] = ts[t+1]-ts[t]
};

// Dormand-Prince A tableau (double-evaluated, rounded to f32 like JAX does).
__device__ __constant__ float cA[5][5] = {
    {(float)(1.0 / 5.0), 0.f, 0.f, 0.f, 0.f},
    {(float)(3.0 / 40.0), (float)(9.0 / 40.0), 0.f, 0.f, 0.f},
    {(float)(44.0 / 45.0), (float)(-56.0 / 15.0), (float)(32.0 / 9.0), 0.f, 0.f},
    {(float)(19372.0 / 6561.0), (float)(-25360.0 / 2187.0),
     (float)(64448.0 / 6561.0), (float)(-212.0 / 729.0), 0.f},
    {(float)(9017.0 / 3168.0), (float)(-355.0 / 33.0),
     (float)(46732.0 / 5247.0), (float)(49.0 / 176.0),
     (float)(-5103.0 / 18656.0)},
};

// tanh(x) = 1 - 2/(exp(2x)+1); ex2.approx/rcp.approx are ~1-ulp class, and the
// formula saturates correctly at +-inf exponent overflow/underflow.
static __device__ __forceinline__ float tanh_fast(float x) {
    float e, r;
    asm("ex2.approx.f32 %0, %1;" : "=f"(e) : "f"(x * 2.8853900817779268f)); // 2*log2(e)
    asm("rcp.approx.f32 %0, %1;" : "=f"(r) : "f"(e + 1.0f));
    return fmaf(-2.0f, r, 1.0f);
}

// Vector field f: R^2 -> R^2, tanh MLP 2 -> 64 -> 64 -> 2, one element per thread.
static __device__ __forceinline__ void evalf(const SW& s, float x, float y,
                                             float& ox, float& oy) {
    float h1[HH];
#pragma unroll
    for (int j = 0; j < HH; j++) {
        float a = fmaf(y, s.W1[2 * j + 1], s.b1[j]);
        a = fmaf(x, s.W1[2 * j], a);
        h1[j] = tanh_fast(a);
    }

    float ax = s.b3[0], ay = s.b3[1];
    const float4* w2 = reinterpret_cast<const float4*>(&s.W2T[0][0]);

#pragma unroll 1  // keep code small: 8 iterations of a fully-unrolled k-loop
    for (int j0 = 0; j0 < HH; j0 += 8) {
        float a0 = s.b2[j0 + 0], a1 = s.b2[j0 + 1];
        float a2 = s.b2[j0 + 2], a3 = s.b2[j0 + 3];
        float a4 = s.b2[j0 + 4], a5 = s.b2[j0 + 5];
        float a6 = s.b2[j0 + 6], a7 = s.b2[j0 + 7];
        const int jq = j0 >> 2;
#pragma unroll
        for (int k = 0; k < HH; k++) {
            float4 wA = w2[k * 16 + jq];       // W2T[k][j0..j0+3]
            float4 wB = w2[k * 16 + jq + 1];   // W2T[k][j0+4..j0+7]
            float hk = h1[k];
            a0 = fmaf(hk, wA.x, a0);
            a1 = fmaf(hk, wA.y, a1);
            a2 = fmaf(hk, wA.z, a2);
            a3 = fmaf(hk, wA.w, a3);
            a4 = fmaf(hk, wB.x, a4);
            a5 = fmaf(hk, wB.y, a5);
            a6 = fmaf(hk, wB.z, a6);
            a7 = fmaf(hk, wB.w, a7);
        }
        a0 = tanh_fast(a0); a1 = tanh_fast(a1);
        a2 = tanh_fast(a2); a3 = tanh_fast(a3);
        a4 = tanh_fast(a4); a5 = tanh_fast(a5);
        a6 = tanh_fast(a6); a7 = tanh_fast(a7);
        ax = fmaf(a0, s.W3P[2 * (j0 + 0) + 0], ax);
        ay = fmaf(a0, s.W3P[2 * (j0 + 0) + 1], ay);
        ax = fmaf(a1, s.W3P[2 * (j0 + 1) + 0], ax);
        ay = fmaf(a1, s.W3P[2 * (j0 + 1) + 1], ay);
        ax = fmaf(a2, s.W3P[2 * (j0 + 2) + 0], ax);
        ay = fmaf(a2, s.W3P[2 * (j0 + 2) + 1], ay);
        ax = fmaf(a3, s.W3P[2 * (j0 + 3) + 0], ax);
        ay = fmaf(a3, s.W3P[2 * (j0 + 3) + 1], ay);
        ax = fmaf(a4, s.W3P[2 * (j0 + 4) + 0], ax);
        ay = fmaf(a4, s.W3P[2 * (j0 + 4) + 1], ay);
        ax = fmaf(a5, s.W3P[2 * (j0 + 5) + 0], ax);
        ay = fmaf(a5, s.W3P[2 * (j0 + 5) + 1], ay);
        ax = fmaf(a6, s.W3P[2 * (j0 + 6) + 0], ax);
        ay = fmaf(a6, s.W3P[2 * (j0 + 6) + 1], ay);
        ax = fmaf(a7, s.W3P[2 * (j0 + 7) + 0], ax);
        ay = fmaf(a7, s.W3P[2 * (j0 + 7) + 1], ay);
    }
    ox = ax;
    oy = ay;
}

__global__ void __launch_bounds__(TPB)
ode_kernel(const float* __restrict__ y0, const float* __restrict__ ts,
           const float* __restrict__ W1, const float* __restrict__ b1,
           const float* __restrict__ W2, const float* __restrict__ b2,
           const float* __restrict__ W3, const float* __restrict__ b3,
           float* __restrict__ out) {
    __shared__ SW s;
    const int tid = threadIdx.x;

    for (int i = tid; i < HH * HH; i += TPB) s.W2T[i & 63][i >> 6] = W2[i];
    for (int i = tid; i < HH * 2; i += TPB) s.W1[i] = W1[i];
    for (int i = tid; i < HH; i += TPB) { s.b1[i] = b1[i]; s.b2[i] = b2[i]; }
    for (int i = tid; i < HH * 2; i += TPB) s.W3P[(i & 63) * 2 + (i >> 6)] = W3[i];
    if (tid < 2) s.b3[tid] = b3[tid];
    for (int i = tid; i < NT - 1; i += TPB) s.dt[i] = ts[i + 1] - ts[i];
    __syncthreads();

    const int e = blockIdx.x * TPB + tid;
    float2 yin = reinterpret_cast<const float2*>(y0)[e];
    float yx = yin.x, yy = yin.y;

    float2* o2 = reinterpret_cast<float2*>(out);
    o2[e] = make_float2(yx, yy);  // SaveAt includes the initial state

    const float B1 = (float)(35.0 / 384.0);
    const float B3 = (float)(500.0 / 1113.0);
    const float B4 = (float)(125.0 / 192.0);
    const float B5 = (float)(-2187.0 / 6784.0);
    const float B6 = (float)(11.0 / 84.0);

    for (int t = 0; t < NT - 1; t++) {
        const float dt = s.dt[t];
        float kx[6], ky[6];
        float sxv = yx, syv = yy;
#pragma unroll 1  // one inlined evalf body; k's spill to local (tiny traffic)
        for (int st = 0; st < 6; st++) {
            float fx, fy;
            evalf(s, sxv, syv, fx, fy);
            kx[st] = fx;
            ky[st] = fy;
            if (st < 5) {
                float accx = 0.f, accy = 0.f;
                for (int i = 0; i <= st; i++) {
                    float a = cA[st][i];
                    accx = fmaf(a, kx[i], accx);
                    accy = fmaf(a, ky[i], accy);
                }
                sxv = fmaf(dt, accx, yx);
                syv = fmaf(dt, accy, yy);
            }
        }
        float accx = B1 * kx[0];
        accx = fmaf(B3, kx[2], accx);
        accx = fmaf(B4, kx[3], accx);
        accx = fmaf(B5, kx[4], accx);
        accx = fmaf(B6, kx[5], accx);
        float accy = B1 * ky[0];
        accy = fmaf(B3, ky[2], accy);
        accy = fmaf(B4, ky[3], accy);
        accy = fmaf(B5, ky[4], accy);
        accy = fmaf(B6, ky[5], accy);
        yx = fmaf(dt, accx, yx);
        yy = fmaf(dt, accy, yy);

        o2[(t + 1) * NB + e] = make_float2(yx, yy);
    }
}

extern "C" void kernel_launch(void* const* d_in, const int* in_sizes, int n_in,
                              void* d_out, int out_size) {
    const float* y0 = (const float*)d_in[0];
    const float* ts = (const float*)d_in[1];
    const float* W1 = (const float*)d_in[2];
    const float* b1 = (const float*)d_in[3];
    const float* W2 = (const float*)d_in[4];
    const float* b2 = (const float*)d_in[5];
    const float* W3 = (const float*)d_in[6];
    const float* b3 = (const float*)d_in[7];
    ode_kernel<<<NB / TPB, TPB>>>(y0, ts, W1, b1, W2, b2, W3, b3, (float*)d_out);
}

// round 2
// speedup vs baseline: 1.0444x; 1.0444x over previous
#include <cuda_runtime.h>

#define NB 16384
#define NT 1024
#define HH 64
#define TPB 64          // 16 elements/block, 4 lanes per element
#define GRID (NB * 4 / TPB)

typedef unsigned long long u64;

// ---- packed f32x2 helpers (Blackwell FFMA2 path; only reachable via PTX) ----
static __device__ __forceinline__ u64 fma2(u64 a, u64 b, u64 c) {
    u64 d;
    asm("fma.rn.f32x2 %0, %1, %2, %3;" : "=l"(d) : "l"(a), "l"(b), "l"(c));
    return d;
}
static __device__ __forceinline__ u64 pk(float a, float b) {
    u64 d;
    asm("mov.b64 %0, {%1, %2};" : "=l"(d) : "f"(a), "f"(b));
    return d;
}
static __device__ __forceinline__ u64 dup2(float a) {
    u64 d;
    asm("mov.b64 %0, {%1, %1};" : "=l"(d) : "f"(a));
    return d;
}
static __device__ __forceinline__ void upk(u64 v, float& a, float& b) {
    asm("mov.b64 {%0, %1}, %2;" : "=f"(a), "=f"(b) : "l"(v));
}

// tanh(x) = 1 - 2/(exp(2x)+1), ex2/rcp approx (~1 ulp class). Validated at
// rel_err 3.4e-7 in round 1.
static __device__ __forceinline__ float tanh_fast(float x) {
    float e, r;
    asm("ex2.approx.f32 %0, %1;" : "=f"(e) : "f"(x * 2.8853900817779268f));
    asm("rcp.approx.f32 %0, %1;" : "=f"(r) : "f"(e + 1.0f));
    return fmaf(-2.0f, r, 1.0f);
}

struct __align__(16) SW {
    float W2T[HH][HH];   // W2T[k][j] = W2[j][k] ; rows are j-contiguous
    float W1x[HH];       // W1[j][0]
    float W1y[HH];       // W1[j][1]
    float b1[HH];
    float b2[HH];
    float W3P[HH * 2];   // W3P[2j+d] = W3[d][j]  (output-pairs per hidden j)
    float b3[2];
    float dt[NT];
};

__device__ __constant__ float cA[5][5] = {
    {(float)(1.0 / 5.0), 0.f, 0.f, 0.f, 0.f},
    {(float)(3.0 / 40.0), (float)(9.0 / 40.0), 0.f, 0.f, 0.f},
    {(float)(44.0 / 45.0), (float)(-56.0 / 15.0), (float)(32.0 / 9.0), 0.f, 0.f},
    {(float)(19372.0 / 6561.0), (float)(-25360.0 / 2187.0),
     (float)(64448.0 / 6561.0), (float)(-212.0 / 729.0), 0.f},
    {(float)(9017.0 / 3168.0), (float)(-355.0 / 33.0),
     (float)(46732.0 / 5247.0), (float)(49.0 / 176.0),
     (float)(-5103.0 / 18656.0)},
};

// f: R^2 -> R^2 cooperatively over a 4-lane quad. Lane q owns hidden units
// [16q, 16q+16). h1 exchanged via padded shared row (66-word stride:
// conflict-free for the warp's 8 rows). Returns the full (fx, fy) on all lanes.
static __device__ __forceinline__ void evalf(const SW& s, float* hrow, int u0,
                                             float x, float y,
                                             float& fx, float& fy) {
    __syncwarp();  // previous f-eval's readers are done before we overwrite
    const u64 xx = dup2(x), yy = dup2(y);
#pragma unroll
    for (int up = 0; up < 8; up++) {
        const int u = u0 + 2 * up;
        u64 a = *(const u64*)&s.b1[u];
        a = fma2(xx, *(const u64*)&s.W1x[u], a);
        a = fma2(yy, *(const u64*)&s.W1y[u], a);
        float a0, a1;
        upk(a, a0, a1);
        *(u64*)&hrow[u] = pk(tanh_fast(a0), tanh_fast(a1));
    }
    __syncwarp();

    u64 acc[8];
#pragma unroll
    for (int jp = 0; jp < 8; jp++) acc[jp] = *(const u64*)&s.b2[u0 + 2 * jp];

#pragma unroll 4
    for (int kp = 0; kp < 32; kp++) {
        const float2 hp = *(const float2*)&hrow[2 * kp];
        const u64 pa = dup2(hp.x), pb = dup2(hp.y);
        const u64* r0 = (const u64*)&s.W2T[2 * kp][u0];
        const u64* r1 = (const u64*)&s.W2T[2 * kp + 1][u0];
#pragma unroll
        for (int jp = 0; jp < 8; jp++) {
            acc[jp] = fma2(pa, r0[jp], acc[jp]);
            acc[jp] = fma2(pb, r1[jp], acc[jp]);
        }
    }

    u64 accP = 0ull;  // packed (0.f, 0.f)
#pragma unroll
    for (int jp = 0; jp < 8; jp++) {
        float h0, h1;
        upk(acc[jp], h0, h1);
        h0 = tanh_fast(h0);
        h1 = tanh_fast(h1);
        const int j = u0 + 2 * jp;
        accP = fma2(dup2(h0), *(const u64*)&s.W3P[2 * j], accP);
        accP = fma2(dup2(h1), *(const u64*)&s.W3P[2 * j + 2], accP);
    }
    float px, py;
    upk(accP, px, py);
    px += __shfl_xor_sync(0xffffffffu, px, 1);
    py += __shfl_xor_sync(0xffffffffu, py, 1);
    px += __shfl_xor_sync(0xffffffffu, px, 2);
    py += __shfl_xor_sync(0xffffffffu, py, 2);
    fx = px + s.b3[0];
    fy = py + s.b3[1];
}

__global__ void __launch_bounds__(TPB, 7)
ode_kernel(const float* __restrict__ y0, const float* __restrict__ ts,
           const float* __restrict__ W1, const float* __restrict__ b1,
           const float* __restrict__ W2, const float* __restrict__ b2,
           const float* __restrict__ W3, const float* __restrict__ b3,
           float* __restrict__ out) {
    __shared__ SW s;
    __shared__ __align__(16) float h1buf[16][66];  // 66-word rows: bank-safe

    const int tid = threadIdx.x;
    for (int i = tid; i < HH * HH; i += TPB) s.W2T[i & 63][i >> 6] = W2[i];
    for (int i = tid; i < HH; i += TPB) {
        s.W1x[i] = W1[2 * i];
        s.W1y[i] = W1[2 * i + 1];
        s.b1[i] = b1[i];
        s.b2[i] = b2[i];
    }
    for (int i = tid; i < HH * 2; i += TPB) s.W3P[(i & 63) * 2 + (i >> 6)] = W3[i];
    if (tid < 2) s.b3[tid] = b3[tid];
    for (int i = tid; i < NT - 1; i += TPB) s.dt[i] = ts[i + 1] - ts[i];
    __syncthreads();

    const int q = tid & 3;           // lane within the element-quad
    const int row = tid >> 2;        // element within block (0..15)
    const int u0 = q * 16;           // this lane's hidden-unit slice base
    float* hrow = h1buf[row];
    const int e = blockIdx.x * (TPB / 4) + row;

    const float2 yin = reinterpret_cast<const float2*>(y0)[e];
    float yx = yin.x, yy = yin.y;

    float2* o2 = reinterpret_cast<float2*>(out);
    if (q == 0) o2[e] = make_float2(yx, yy);  // SaveAt includes initial state

    const float B1 = (float)(35.0 / 384.0);
    const float B3 = (float)(500.0 / 1113.0);
    const float B4 = (float)(125.0 / 192.0);
    const float B5 = (float)(-2187.0 / 6784.0);
    const float B6 = (float)(11.0 / 84.0);

    for (int t = 0; t < NT - 1; t++) {
        const float dt = s.dt[t];
        float kx[6], ky[6];
        float sxv = yx, syv = yy;
#pragma unroll 1  // single inlined evalf body; keeps I$ small
        for (int st = 0; st < 6; st++) {
            float fx, fy;
            evalf(s, hrow, u0, sxv, syv, fx, fy);
            kx[st] = fx;
            ky[st] = fy;
            if (st < 5) {
                float accx = 0.f, accy = 0.f;
                for (int i = 0; i <= st; i++) {
                    const float a = cA[st][i];
                    accx = fmaf(a, kx[i], accx);
                    accy = fmaf(a, ky[i], accy);
                }
                sxv = fmaf(dt, accx, yx);
                syv = fmaf(dt, accy, yy);
            }
        }
        float accx = B1 * kx[0];
        accx = fmaf(B3, kx[2], accx);
        accx = fmaf(B4, kx[3], accx);
        accx = fmaf(B5, kx[4], accx);
        accx = fmaf(B6, kx[5], accx);
        float accy = B1 * ky[0];
        accy = fmaf(B3, ky[2], accy);
        accy = fmaf(B4, ky[3], accy);
        accy = fmaf(B5, ky[4], accy);
        accy = fmaf(B6, ky[5], accy);
        yx = fmaf(dt, accx, yx);
        yy = fmaf(dt, accy, yy);

        if (q == 0) o2[(t + 1) * NB + e] = make_float2(yx, yy);
    }
}

extern "C" void kernel_launch(void* const* d_in, const int* in_sizes, int n_in,
                              void* d_out, int out_size) {
    const float* y0 = (const float*)d_in[0];
    const float* ts = (const float*)d_in[1];
    const float* W1 = (const float*)d_in[2];
    const float* b1 = (const float*)d_in[3];
    const float* W2 = (const float*)d_in[4];
    const float* b2 = (const float*)d_in[5];
    const float* W3 = (const float*)d_in[6];
    const float* b3 = (const float*)d_in[7];
    ode_kernel<<<GRID, TPB>>>(y0, ts, W1, b1, W2, b2, W3, b3, (float*)d_out);
}

// round 3
// speedup vs baseline: 3.2780x; 3.1385x over previous
#include <cuda_runtime.h>

#define NB 16384
#define NT 1024
#define HH 64
#define TPB 256
#define WPB 8                 // warps/block
#define EPW 16                // elements/warp (4 g-groups x 4 elements)
#define EPB (WPB * EPW)       // 128 elements/block
#define GRID (NB / EPB)       // 128 blocks

typedef unsigned long long u64;

// ---- packed f32x2 (Blackwell FFMA2 path, PTX-only) ----
static __device__ __forceinline__ u64 fma2(u64 a, u64 b, u64 c) {
    u64 d;
    asm("fma.rn.f32x2 %0, %1, %2, %3;" : "=l"(d) : "l"(a), "l"(b), "l"(c));
    return d;
}
static __device__ __forceinline__ u64 dup2(float a) {
    u64 d;
    asm("mov.b64 %0, {%1, %1};" : "=l"(d) : "f"(a));
    return d;
}
static __device__ __forceinline__ void upk(u64 v, float& a, float& b) {
    asm("mov.b64 {%0, %1}, %2;" : "=f"(a), "=f"(b) : "l"(v));
}

// tanh(x) = 1 - 2/(exp(2x)+1); validated at rel_err 3.4e-7 over 1023 steps.
static __device__ __forceinline__ float tanh_fast(float x) {
    float e, r;
    asm("ex2.approx.f32 %0, %1;" : "=f"(e) : "f"(x * 2.8853900817779268f));
    asm("rcp.approx.f32 %0, %1;" : "=f"(r) : "f"(e + 1.0f));
    return fmaf(-2.0f, r, 1.0f);
}

struct __align__(16) SW {
    // W2 rows with 16B-block permutation p(b) = (b&1)*8 + (b>>1) so the 8
    // per-lane chunks of one LDS.128 cover all 32 banks (conflict-free).
    float W2s[HH][HH];
    float W1x[HH], W1y[HH], b1[HH], b2[HH];
    float W3P[HH * 2];        // W3P[2u+d] = W3[d][u]
    float b3[2];
    float dt[NT];
};

__device__ __constant__ float cA[5][5] = {
    {(float)(1.0 / 5.0), 0.f, 0.f, 0.f, 0.f},
    {(float)(3.0 / 40.0), (float)(9.0 / 40.0), 0.f, 0.f, 0.f},
    {(float)(44.0 / 45.0), (float)(-56.0 / 15.0), (float)(32.0 / 9.0), 0.f, 0.f},
    {(float)(19372.0 / 6561.0), (float)(-25360.0 / 2187.0),
     (float)(64448.0 / 6561.0), (float)(-212.0 / 729.0), 0.f},
    {(float)(9017.0 / 3168.0), (float)(-355.0 / 33.0),
     (float)(46732.0 / 5247.0), (float)(49.0 / 176.0),
     (float)(-5103.0 / 18656.0)},
};

__global__ void __launch_bounds__(TPB)
ode_kernel(const float* __restrict__ y0, const float* __restrict__ ts,
           const float* __restrict__ W1, const float* __restrict__ b1,
           const float* __restrict__ W2, const float* __restrict__ b2,
           const float* __restrict__ W3, const float* __restrict__ b3,
           float* __restrict__ out) {
    __shared__ SW s;
    __shared__ __align__(16) float hT[WPB][HH][EPW];   // [unit][elem], 32 KB
    __shared__ __align__(8) float2 kb[WPB][6][EPW];    // RK stage k's, 6 KB

    const int tid = threadIdx.x;
    for (int i = tid; i < HH * HH; i += TPB) {
        const int j = i >> 6, k = i & 63;        // W2[j][k] -> W2T[k][j]
        const int b = j >> 2, w = j & 3;
        const int p = ((b & 1) << 3) + (b >> 1); // block permutation
        s.W2s[k][p * 4 + w] = W2[i];
    }
    for (int i = tid; i < HH; i += TPB) {
        s.W1x[i] = W1[2 * i];
        s.W1y[i] = W1[2 * i + 1];
        s.b1[i] = b1[i];
        s.b2[i] = b2[i];
    }
    for (int i = tid; i < HH * 2; i += TPB) {
        const int d = i >> 6, u = i & 63;
        s.W3P[2 * u + d] = W3[i];
    }
    if (tid < 2) s.b3[tid] = b3[tid];
    for (int i = tid; i < NT - 1; i += TPB) s.dt[i] = ts[i + 1] - ts[i];
    __syncthreads();

    const int wid = tid >> 5, lane = tid & 31;
    const int o = lane & 7;        // hidden slice: units 8o..8o+7
    const int g = lane >> 3;       // element sub-group: elements 4g..4g+3
    float* hw = &hT[wid][0][0];
    float2* kw = &kb[wid][0][0];
    const int eloc = 4 * g;                          // warp-local element base
    const int e0 = blockIdx.x * EPB + wid * EPW + eloc;

    float yx[4], yy[4];
#pragma unroll
    for (int m = 0; m < 4; m++) {
        const float2 v = reinterpret_cast<const float2*>(y0)[e0 + m];
        yx[m] = v.x;
        yy[m] = v.y;
    }

    float2* o2 = reinterpret_cast<float2*>(out);
    if (o == 0) {  // SaveAt includes the initial state
        *(float4*)&o2[e0]     = make_float4(yx[0], yy[0], yx[1], yy[1]);
        *(float4*)&o2[e0 + 2] = make_float4(yx[2], yy[2], yx[3], yy[3]);
    }

    const float B1 = (float)(35.0 / 384.0);
    const float B3 = (float)(500.0 / 1113.0);
    const float B4 = (float)(125.0 / 192.0);
    const float B5 = (float)(-2187.0 / 6784.0);
    const float B6 = (float)(11.0 / 84.0);

    for (int t = 0; t < NT - 1; t++) {
        const float dt = s.dt[t];
        float sx[4], sy[4];
#pragma unroll
        for (int m = 0; m < 4; m++) { sx[m] = yx[m]; sy[m] = yy[m]; }

#pragma unroll 1  // single inlined f-eval body (I$-friendly)
        for (int st = 0; st < 6; st++) {
            __syncwarp();  // prior readers of hT are done

            // ---- layer 1: units 8o+i, elements 4g+m -> hT[u][elem] ----
#pragma unroll
            for (int i = 0; i < 8; i++) {
                const int u = 8 * o + i;
                const float w1x = s.W1x[u], w1y = s.W1y[u], bb = s.b1[u];
                float hv[4];
#pragma unroll
                for (int m = 0; m < 4; m++)
                    hv[m] = tanh_fast(fmaf(sx[m], w1x, fmaf(sy[m], w1y, bb)));
                *(float4*)&hw[u * EPW + eloc] =
                    make_float4(hv[0], hv[1], hv[2], hv[3]);
            }
            __syncwarp();

            // ---- layer 2: acc[m][p] over unit-pairs (8o+2p, 8o+2p+1) ----
            u64 acc[4][4];
#pragma unroll
            for (int p = 0; p < 4; p++) {
                const u64 bp = *(const u64*)&s.b2[8 * o + 2 * p];
#pragma unroll
                for (int m = 0; m < 4; m++) acc[m][p] = bp;
            }
#pragma unroll 8
            for (int k = 0; k < HH; k++) {
                const float4 hv = *(const float4*)&hw[k * EPW + eloc];
                const u64 h0 = dup2(hv.x), h1 = dup2(hv.y);
                const u64 h2 = dup2(hv.z), h3 = dup2(hv.w);
                const float4 wA = *(const float4*)&s.W2s[k][4 * o];
                const float4 wB = *(const float4*)&s.W2s[k][32 + 4 * o];
                const u64 w0 = ((const u64*)&wA)[0], w1 = ((const u64*)&wA)[1];
                const u64 w2v = ((const u64*)&wB)[0], w3v = ((const u64*)&wB)[1];
                acc[0][0] = fma2(h0, w0, acc[0][0]);
                acc[0][1] = fma2(h0, w1, acc[0][1]);
                acc[0][2] = fma2(h0, w2v, acc[0][2]);
                acc[0][3] = fma2(h0, w3v, acc[0][3]);
                acc[1][0] = fma2(h1, w0, acc[1][0]);
                acc[1][1] = fma2(h1, w1, acc[1][1]);
                acc[1][2] = fma2(h1, w2v, acc[1][2]);
                acc[1][3] = fma2(h1, w3v, acc[1][3]);
                acc[2][0] = fma2(h2, w0, acc[2][0]);
                acc[2][1] = fma2(h2, w1, acc[2][1]);
                acc[2][2] = fma2(h2, w2v, acc[2][2]);
                acc[2][3] = fma2(h2, w3v, acc[2][3]);
                acc[3][0] = fma2(h3, w0, acc[3][0]);
                acc[3][1] = fma2(h3, w1, acc[3][1]);
                acc[3][2] = fma2(h3, w2v, acc[3][2]);
                acc[3][3] = fma2(h3, w3v, acc[3][3]);
            }

            // ---- layer-2 tanh + layer 3 (partial over this lane's units) ----
            u64 accP[4] = {0ull, 0ull, 0ull, 0ull};
#pragma unroll
            for (int p = 0; p < 4; p++) {
                const u64 wp0 = *(const u64*)&s.W3P[16 * o + 4 * p];
                const u64 wp1 = *(const u64*)&s.W3P[16 * o + 4 * p + 2];
#pragma unroll
                for (int m = 0; m < 4; m++) {
                    float a0, a1;
                    upk(acc[m][p], a0, a1);
                    accP[m] = fma2(dup2(tanh_fast(a0)), wp0, accP[m]);
                    accP[m] = fma2(dup2(tanh_fast(a1)), wp1, accP[m]);
                }
            }

            // reduce over the 8 o-lanes (lane = g*8+o -> xor 1,2,4 stays in group)
            float fx[4], fy[4];
#pragma unroll
            for (int m = 0; m < 4; m++) {
                float px, py;
                upk(accP[m], px, py);
                px += __shfl_xor_sync(0xffffffffu, px, 1);
                py += __shfl_xor_sync(0xffffffffu, py, 1);
                px += __shfl_xor_sync(0xffffffffu, px, 2);
                py += __shfl_xor_sync(0xffffffffu, py, 2);
                px += __shfl_xor_sync(0xffffffffu, px, 4);
                py += __shfl_xor_sync(0xffffffffu, py, 4);
                fx[m] = px + s.b3[0];
                fy[m] = py + s.b3[1];
            }
            if (o == 0) {
#pragma unroll
                for (int m = 0; m < 4; m++)
                    kw[st * EPW + eloc + m] = make_float2(fx[m], fy[m]);
            }
            __syncwarp();

            if (st < 5) {  // next stage input (redundant on all lanes)
#pragma unroll
                for (int m = 0; m < 4; m++) {
                    float ax = 0.f, ay = 0.f;
                    for (int i = 0; i <= st; i++) {
                        const float a = cA[st][i];
                        const float2 kv = kw[i * EPW + eloc + m];
                        ax = fmaf(a, kv.x, ax);
                        ay = fmaf(a, kv.y, ay);
                    }
                    sx[m] = fmaf(dt, ax, yx[m]);
                    sy[m] = fmaf(dt, ay, yy[m]);
                }
            }
        }

        // ---- combine and advance ----
#pragma unroll
        for (int m = 0; m < 4; m++) {
            const float2 k1 = kw[0 * EPW + eloc + m];
            const float2 k3 = kw[2 * EPW + eloc + m];
            const float2 k4 = kw[3 * EPW + eloc + m];
            const float2 k5 = kw[4 * EPW + eloc + m];
            const float2 k6 = kw[5 * EPW + eloc + m];
            float ax = B1 * k1.x, ay = B1 * k1.y;
            ax = fmaf(B3, k3.x, ax); ay = fmaf(B3, k3.y, ay);
            ax = fmaf(B4, k4.x, ax); ay = fmaf(B4, k4.y, ay);
            ax = fmaf(B5, k5.x, ax); ay = fmaf(B5, k5.y, ay);
            ax = fmaf(B6, k6.x, ax); ay = fmaf(B6, k6.y, ay);
            yx[m] = fmaf(dt, ax, yx[m]);
            yy[m] = fmaf(dt, ay, yy[m]);
        }
        if (o == 0) {
            float2* orow = o2 + (size_t)(t + 1) * NB;
            *(float4*)&orow[e0]     = make_float4(yx[0], yy[0], yx[1], yy[1]);
            *(float4*)&orow[e0 + 2] = make_float4(yx[2], yy[2], yx[3], yy[3]);
        }
    }
}

extern "C" void kernel_launch(void* const* d_in, const int* in_sizes, int n_in,
                              void* d_out, int out_size) {
    const float* y0 = (const float*)d_in[0];
    const float* ts = (const float*)d_in[1];
    const float* W1 = (const float*)d_in[2];
    const float* b1 = (const float*)d_in[3];
    const float* W2 = (const float*)d_in[4];
    const float* b2 = (const float*)d_in[5];
    const float* W3 = (const float*)d_in[6];
    const float* b3 = (const float*)d_in[7];
    ode_kernel<<<GRID, TPB>>>(y0, ts, W1, b1, W2, b2, W3, b3, (float*)d_out);
}

// round 4
// speedup vs baseline: 3.5722x; 1.0898x over previous
#include <cuda_runtime.h>

#define NB 16384
#define NT 1024
#define HH 64
#define TPB 128
#define WPB 4                 // warps/block
#define EPW 16                // elements/warp (4 g-groups x 4 elements)
#define EPB (WPB * EPW)       // 64 elements/block
#define GRID (NB / EPB)       // 256 blocks

typedef unsigned long long u64;

// ---- packed f32x2 (Blackwell FFMA2 path, PTX-only) ----
static __device__ __forceinline__ u64 fma2(u64 a, u64 b, u64 c) {
    u64 d;
    asm("fma.rn.f32x2 %0, %1, %2, %3;" : "=l"(d) : "l"(a), "l"(b), "l"(c));
    return d;
}
static __device__ __forceinline__ u64 dup2(float a) {
    u64 d;
    asm("mov.b64 %0, {%1, %1};" : "=l"(d) : "f"(a));
    return d;
}
static __device__ __forceinline__ void upk(u64 v, float& a, float& b) {
    asm("mov.b64 {%0, %1}, %2;" : "=f"(a), "=f"(b) : "l"(v));
}

// tanh(x) = 1 - 2/(exp(2x)+1); validated at rel_err ~3.6e-7 over 1023 steps.
static __device__ __forceinline__ float tanh_fast(float x) {
    float e, r;
    asm("ex2.approx.f32 %0, %1;" : "=f"(e) : "f"(x * 2.8853900817779268f));
    asm("rcp.approx.f32 %0, %1;" : "=f"(r) : "f"(e + 1.0f));
    return fmaf(-2.0f, r, 1.0f);
}

struct __align__(16) SW {
    // W2 rows, 16B-block permutation p(b) = (b&1)*8 + (b>>1): the two per-k
    // LDS.128 each touch 8 distinct 16B chunks spanning all 32 banks.
    float W2s[HH][HH];
    float W1x[HH], W1y[HH], b1[HH], b2[HH];
    float W3P[HH * 2];        // W3P[2u+d] = W3[d][u]
    float b3[2];
    float dt[NT];
};

__device__ __constant__ float cA[5][5] = {
    {(float)(1.0 / 5.0), 0.f, 0.f, 0.f, 0.f},
    {(float)(3.0 / 40.0), (float)(9.0 / 40.0), 0.f, 0.f, 0.f},
    {(float)(44.0 / 45.0), (float)(-56.0 / 15.0), (float)(32.0 / 9.0), 0.f, 0.f},
    {(float)(19372.0 / 6561.0), (float)(-25360.0 / 2187.0),
     (float)(64448.0 / 6561.0), (float)(-212.0 / 729.0), 0.f},
    {(float)(9017.0 / 3168.0), (float)(-355.0 / 33.0),
     (float)(46732.0 / 5247.0), (float)(49.0 / 176.0),
     (float)(-5103.0 / 18656.0)},
};

__global__ void __launch_bounds__(TPB)
ode_kernel(const float* __restrict__ y0, const float* __restrict__ ts,
           const float* __restrict__ W1, const float* __restrict__ b1,
           const float* __restrict__ W2, const float* __restrict__ b2,
           const float* __restrict__ W3, const float* __restrict__ b3,
           float* __restrict__ out) {
    __shared__ SW s;
    __shared__ __align__(16) float hT[WPB][HH][EPW];   // [unit][elem], 16 KB

    const int tid = threadIdx.x;
    for (int i = tid; i < HH * HH; i += TPB) {
        const int j = i >> 6, k = i & 63;        // W2[j][k] -> transposed
        const int b = j >> 2, w = j & 3;
        const int p = ((b & 1) << 3) + (b >> 1); // block permutation
        s.W2s[k][p * 4 + w] = W2[i];
    }
    for (int i = tid; i < HH; i += TPB) {
        s.W1x[i] = W1[2 * i];
        s.W1y[i] = W1[2 * i + 1];
        s.b1[i] = b1[i];
        s.b2[i] = b2[i];
    }
    for (int i = tid; i < HH * 2; i += TPB) {
        const int d = i >> 6, u = i & 63;
        s.W3P[2 * u + d] = W3[i];
    }
    if (tid < 2) s.b3[tid] = b3[tid];
    for (int i = tid; i < NT - 1; i += TPB) s.dt[i] = ts[i + 1] - ts[i];
    __syncthreads();

    const int wid = tid >> 5, lane = tid & 31;
    const int o = lane & 7;        // hidden slice: units 8o..8o+7
    const int g = lane >> 3;       // element sub-group: elements 4g..4g+3
    float* hw = &hT[wid][0][0];
    const int eloc = 4 * g;                          // warp-local element base
    const int e0 = blockIdx.x * EPB + wid * EPW + eloc;

    float yx[4], yy[4];
#pragma unroll
    for (int m = 0; m < 4; m++) {
        const float2 v = reinterpret_cast<const float2*>(y0)[e0 + m];
        yx[m] = v.x;
        yy[m] = v.y;
    }

    float2* o2 = reinterpret_cast<float2*>(out);
    if (o == 0) {  // SaveAt includes the initial state
        *(float4*)&o2[e0]     = make_float4(yx[0], yy[0], yx[1], yy[1]);
        *(float4*)&o2[e0 + 2] = make_float4(yx[2], yy[2], yx[3], yy[3]);
    }

    const float B1 = (float)(35.0 / 384.0);
    const float B3 = (float)(500.0 / 1113.0);
    const float B4 = (float)(125.0 / 192.0);
    const float B5 = (float)(-2187.0 / 6784.0);
    const float B6 = (float)(11.0 / 84.0);

    for (int t = 0; t < NT - 1; t++) {
        const float dt = s.dt[t];
        float sx[4], sy[4];
        float kxr[6][4], kyr[6][4];   // RK stage values, register-resident
#pragma unroll
        for (int m = 0; m < 4; m++) { sx[m] = yx[m]; sy[m] = yy[m]; }

#pragma unroll 1  // single inlined f-eval body (I$-friendly)
        for (int st = 0; st < 6; st++) {
            __syncwarp();  // prior stage's hT readers are done (WAR)

            // ---- layer 1: units 8o+i, elements 4g+m -> hT[u][elem] ----
#pragma unroll
            for (int i = 0; i < 8; i++) {
                const int u = 8 * o + i;
                const float w1x = s.W1x[u], w1y = s.W1y[u], bb = s.b1[u];
                float hv[4];
#pragma unroll
                for (int m = 0; m < 4; m++)
                    hv[m] = tanh_fast(fmaf(sx[m], w1x, fmaf(sy[m], w1y, bb)));
                *(float4*)&hw[u * EPW + eloc] =
                    make_float4(hv[0], hv[1], hv[2], hv[3]);
            }
            __syncwarp();  // hT complete (RAW)

            // ---- layer 2: acc[m][p] over unit-pairs (8o+2p, 8o+2p+1) ----
            u64 acc[4][4];
#pragma unroll
            for (int p = 0; p < 4; p++) {
                const u64 bp = *(const u64*)&s.b2[8 * o + 2 * p];
#pragma unroll
                for (int m = 0; m < 4; m++) acc[m][p] = bp;
            }
#pragma unroll 8
            for (int k = 0; k < HH; k++) {
                const float4 hv = *(const float4*)&hw[k * EPW + eloc];
                const u64 h0 = dup2(hv.x), h1 = dup2(hv.y);
                const u64 h2 = dup2(hv.z), h3 = dup2(hv.w);
                const float4 wA = *(const float4*)&s.W2s[k][4 * o];
                const float4 wB = *(const float4*)&s.W2s[k][32 + 4 * o];
                const u64 w0 = ((const u64*)&wA)[0], w1 = ((const u64*)&wA)[1];
                const u64 w2v = ((const u64*)&wB)[0], w3v = ((const u64*)&wB)[1];
                acc[0][0] = fma2(h0, w0, acc[0][0]);
                acc[0][1] = fma2(h0, w1, acc[0][1]);
                acc[0][2] = fma2(h0, w2v, acc[0][2]);
                acc[0][3] = fma2(h0, w3v, acc[0][3]);
                acc[1][0] = fma2(h1, w0, acc[1][0]);
                acc[1][1] = fma2(h1, w1, acc[1][1]);
                acc[1][2] = fma2(h1, w2v, acc[1][2]);
                acc[1][3] = fma2(h1, w3v, acc[1][3]);
                acc[2][0] = fma2(h2, w0, acc[2][0]);
                acc[2][1] = fma2(h2, w1, acc[2][1]);
                acc[2][2] = fma2(h2, w2v, acc[2][2]);
                acc[2][3] = fma2(h2, w3v, acc[2][3]);
                acc[3][0] = fma2(h3, w0, acc[3][0]);
                acc[3][1] = fma2(h3, w1, acc[3][1]);
                acc[3][2] = fma2(h3, w2v, acc[3][2]);
                acc[3][3] = fma2(h3, w3v, acc[3][3]);
            }

            // ---- layer-2 tanh + layer 3 (partial over this lane's units) ----
            u64 accP[4] = {0ull, 0ull, 0ull, 0ull};
#pragma unroll
            for (int p = 0; p < 4; p++) {
                const u64 wp0 = *(const u64*)&s.W3P[16 * o + 4 * p];
                const u64 wp1 = *(const u64*)&s.W3P[16 * o + 4 * p + 2];
#pragma unroll
                for (int m = 0; m < 4; m++) {
                    float a0, a1;
                    upk(acc[m][p], a0, a1);
                    accP[m] = fma2(dup2(tanh_fast(a0)), wp0, accP[m]);
                    accP[m] = fma2(dup2(tanh_fast(a1)), wp1, accP[m]);
                }
            }

            // xor-butterfly over the 8 o-lanes: EVERY lane ends with the full
            // (fx, fy) — stage k's stay in registers, no shared round-trip.
#pragma unroll
            for (int m = 0; m < 4; m++) {
                float px, py;
                upk(accP[m], px, py);
                px += __shfl_xor_sync(0xffffffffu, px, 1);
                py += __shfl_xor_sync(0xffffffffu, py, 1);
                px += __shfl_xor_sync(0xffffffffu, px, 2);
                py += __shfl_xor_sync(0xffffffffu, py, 2);
                px += __shfl_xor_sync(0xffffffffu, px, 4);
                py += __shfl_xor_sync(0xffffffffu, py, 4);
                kxr[st][m] = px + s.b3[0];
                kyr[st][m] = py + s.b3[1];
            }

            if (st < 5) {  // next stage input (identical on all lanes)
#pragma unroll
                for (int m = 0; m < 4; m++) {
                    float ax = 0.f, ay = 0.f;
                    for (int i = 0; i <= st; i++) {
                        const float a = cA[st][i];
                        ax = fmaf(a, kxr[i][m], ax);
                        ay = fmaf(a, kyr[i][m], ay);
                    }
                    sx[m] = fmaf(dt, ax, yx[m]);
                    sy[m] = fmaf(dt, ay, yy[m]);
                }
            }
        }

        // ---- combine and advance (register-resident stage values) ----
#pragma unroll
        for (int m = 0; m < 4; m++) {
            float ax = B1 * kxr[0][m], ay = B1 * kyr[0][m];
            ax = fmaf(B3, kxr[2][m], ax); ay = fmaf(B3, kyr[2][m], ay);
            ax = fmaf(B4, kxr[3][m], ax); ay = fmaf(B4, kyr[3][m], ay);
            ax = fmaf(B5, kxr[4][m], ax); ay = fmaf(B5, kyr[4][m], ay);
            ax = fmaf(B6, kxr[5][m], ax); ay = fmaf(B6, kyr[5][m], ay);
            yx[m] = fmaf(dt, ax, yx[m]);
            yy[m] = fmaf(dt, ay, yy[m]);
        }
        if (o == 0) {
            float2* orow = o2 + (size_t)(t + 1) * NB;
            *(float4*)&orow[e0]     = make_float4(yx[0], yy[0], yx[1], yy[1]);
            *(float4*)&orow[e0 + 2] = make_float4(yx[2], yy[2], yx[3], yy[3]);
        }
    }
}

extern "C" void kernel_launch(void* const* d_in, const int* in_sizes, int n_in,
                              void* d_out, int out_size) {
    const float* y0 = (const float*)d_in[0];
    const float* ts = (const float*)d_in[1];
    const float* W1 = (const float*)d_in[2];
    const float* b1 = (const float*)d_in[3];
    const float* W2 = (const float*)d_in[4];
    const float* b2 = (const float*)d_in[5];
    const float* W3 = (const float*)d_in[6];
    const float* b3 = (const float*)d_in[7];
    ode_kernel<<<GRID, TPB>>>(y0, ts, W1, b1, W2, b2, W3, b3, (float*)d_out);
}